// round 16
// baseline (speedup 1.0000x reference)
#include <cuda_runtime.h>
#include <cuda_bf16.h>
#include <cuda_fp16.h>
#include <math.h>

// Problem constants
#define BATCH 8
#define SEQ   2048
#define DIM   512
#define KDIM  1024
#define MTOT  (BATCH*SEQ)   // 16384

// Scratch (no cudaMalloc allowed)
__device__ __half g_xf[(size_t)MTOT * KDIM];
__device__ __half g_wf[(size_t)3 * DIM * KDIM];
__device__ __half g_qf[(size_t)MTOT * DIM];
__device__ __half g_kf[(size_t)MTOT * DIM];
__device__ __half g_vf[(size_t)MTOT * DIM];

// ---------------------------------------------------------------------------
// helpers
// ---------------------------------------------------------------------------
__device__ __forceinline__ unsigned smem_u32(const void* p) {
    unsigned a;
    asm("{ .reg .u64 t; cvta.to.shared.u64 t, %1; cvt.u32.u64 %0, t; }" : "=r"(a) : "l"(p));
    return a;
}
__device__ __forceinline__ void cpa16(unsigned dst, const void* src) {
    asm volatile("cp.async.cg.shared.global [%0], [%1], 16;"
                 :: "r"(dst), "l"(__cvta_generic_to_global(src)) : "memory");
}
__device__ __forceinline__ void cp_commit() {
    asm volatile("cp.async.commit_group;" ::: "memory");
}
template <int N>
__device__ __forceinline__ void cp_wait() {
    asm volatile("cp.async.wait_group %0;" :: "n"(N) : "memory");
}
__device__ __forceinline__ void ldsm4(unsigned* r, unsigned addr) {
    asm volatile("ldmatrix.sync.aligned.m8n8.x4.shared.b16 {%0,%1,%2,%3}, [%4];"
                 : "=r"(r[0]), "=r"(r[1]), "=r"(r[2]), "=r"(r[3]) : "r"(addr));
}
__device__ __forceinline__ void ldsm4t(unsigned* r, unsigned addr) {
    asm volatile("ldmatrix.sync.aligned.m8n8.x4.trans.shared.b16 {%0,%1,%2,%3}, [%4];"
                 : "=r"(r[0]), "=r"(r[1]), "=r"(r[2]), "=r"(r[3]) : "r"(addr));
}
__device__ __forceinline__ void mma_f16(float* c, const unsigned* a,
                                        unsigned b0, unsigned b1) {
    asm volatile(
        "mma.sync.aligned.m16n8k16.row.col.f32.f16.f16.f32 "
        "{%0,%1,%2,%3}, {%4,%5,%6,%7}, {%8,%9}, {%0,%1,%2,%3};"
        : "+f"(c[0]), "+f"(c[1]), "+f"(c[2]), "+f"(c[3])
        : "r"(a[0]), "r"(a[1]), "r"(a[2]), "r"(a[3]), "r"(b0), "r"(b1));
}

// ---------------------------------------------------------------------------
// Conversion: x0|x1 -> fp16, row-major [MTOT][1024]
// ---------------------------------------------------------------------------
__global__ __launch_bounds__(256)
void conv_x(const float* __restrict__ x0, const float* __restrict__ x1)
{
    unsigned t = blockIdx.x * 256u + threadIdx.x;
    unsigned m  = t >> 8;
    unsigned k4 = (t & 255u) * 4u;
    float4 v = (k4 < 512u)
        ? *(const float4*)(x0 + (size_t)m * 512 + k4)
        : *(const float4*)(x1 + (size_t)m * 512 + (k4 - 512u));
    __half2* d = (__half2*)(g_xf + (size_t)m * 1024 + k4);
    d[0] = __floats2half2_rn(v.x, v.y);
    d[1] = __floats2half2_rn(v.z, v.w);
}

// ---------------------------------------------------------------------------
// W[k][n] -> W^T fp16, n-major rows (q scaled by 1/sqrt(D))
// ---------------------------------------------------------------------------
__global__ __launch_bounds__(256)
void conv_w(const float* __restrict__ Wq, const float* __restrict__ Wk,
            const float* __restrict__ Wv)
{
    __shared__ float tile[32][33];
    const int z  = blockIdx.z;
    const float* __restrict__ W = (z == 0) ? Wq : ((z == 1) ? Wk : Wv);
    const int n0 = blockIdx.x * 32;
    const int k0 = blockIdx.y * 32;
    const int tx = threadIdx.x;
    const int ty = threadIdx.y;

    for (int r = ty; r < 32; r += 8)
        tile[r][tx] = W[(size_t)(k0 + r) * 512 + n0 + tx];
    __syncthreads();

    const float scale = (z == 0) ? 0.04419417382415922f : 1.0f;
    for (int r = ty; r < 32; r += 8) {
        int n = n0 + r;
        int k = k0 + tx;
        g_wf[((size_t)(z * 512 + n)) * 1024 + k] = __float2half_rn(tile[tx][r] * scale);
    }
}

// ---------------------------------------------------------------------------
// QKV GEMM via mma.sync fp16, A-fragment pipelined. (unchanged — measured good)
// ---------------------------------------------------------------------------
#define GF_BUF 20480
#define GF_SMEM (2 * GF_BUF)

__device__ __forceinline__ void gemm_issue(unsigned sb, int buf, int m0, int nbase,
                                           int k0, int tid)
{
    unsigned base = sb + buf * GF_BUF;
#pragma unroll
    for (int i = 0; i < 4; i++) {
        int idx = tid + i * 256;
        int which = idx >> 9;
        int u = idx & 511;
        int row = u >> 2;
        int c = u & 3;
        const __half* src = which
            ? (g_wf + (size_t)(nbase + row) * 1024 + k0 + c * 8)
            : (g_xf + (size_t)(m0 + row) * 1024 + k0 + c * 8);
        cpa16(base + which * 10240 + row * 80 + c * 16, src);
    }
    cp_commit();
}

__global__ __launch_bounds__(256, 2)
void qkv_hmma()
{
    extern __shared__ char smem[];
    unsigned sb = smem_u32(smem);
    const int tid  = threadIdx.x;
    const int lane = tid & 31;
    const int w    = tid >> 5;
    const int wm   = w >> 2;
    const int wn   = w & 3;
    const int nbase = blockIdx.x * 128;
    const int m0    = blockIdx.y * 128;

    float acc[4][4][4];
#pragma unroll
    for (int i = 0; i < 4; i++)
#pragma unroll
        for (int j = 0; j < 4; j++)
#pragma unroll
            for (int k = 0; k < 4; k++) acc[i][j][k] = 0.0f;

    const int mrowA = (lane & 7) + ((lane >> 3) & 1) * 8;
    const int kcA   = (lane >> 4) & 1;
    const int nrowB = (lane & 7) + ((lane >> 4) & 1) * 8;
    const int kcB   = (lane >> 3) & 1;
    const unsigned aoff = (wm * 64 + mrowA) * 80 + kcA * 16;
    const unsigned boff = 10240u + (wn * 32 + nrowB) * 80 + kcB * 16;

    gemm_issue(sb, 0, m0, nbase, 0, tid);

    for (int ch = 0; ch < 32; ++ch) {
        if (ch + 1 < 32) {
            gemm_issue(sb, (ch + 1) & 1, m0, nbase, (ch + 1) * 32, tid);
            cp_wait<1>();
        } else {
            cp_wait<0>();
        }
        __syncthreads();

        unsigned base = sb + (ch & 1) * GF_BUF;
#pragma unroll
        for (int ks = 0; ks < 2; ks++) {
            unsigned B8[8];
            ldsm4(&B8[0], base + boff + ks * 32);
            ldsm4(&B8[4], base + boff + 16 * 80 + ks * 32);
            unsigned Ab[2][4];
            ldsm4(Ab[0], base + aoff + ks * 32);
#pragma unroll
            for (int mt = 0; mt < 4; mt++) {
                int cur = mt & 1;
                if (mt < 3)
                    ldsm4(Ab[cur ^ 1], base + aoff + (mt + 1) * (16 * 80) + ks * 32);
#pragma unroll
                for (int nt = 0; nt < 4; nt++)
                    mma_f16(acc[mt][nt], Ab[cur], B8[nt * 2], B8[nt * 2 + 1]);
            }
        }
        __syncthreads();
    }

    const int z = nbase >> 9;
    __half* Xf = (z == 0) ? g_qf : ((z == 1) ? g_kf : g_vf);
    const int colb = (nbase & 511) + wn * 32;
    const int gid = lane >> 2, tig = lane & 3;
#pragma unroll
    for (int mt = 0; mt < 4; mt++) {
#pragma unroll
        for (int nt = 0; nt < 4; nt++) {
            int row = m0 + wm * 64 + mt * 16 + gid;
            int col = colb + nt * 8 + tig * 2;
#pragma unroll
            for (int rr = 0; rr < 2; rr++) {
                size_t o = (size_t)(row + rr * 8) * 512 + col;
                *(__half2*)(Xf + o) =
                    __floats2half2_rn(acc[mt][nt][rr * 2 + 0], acc[mt][nt][rr * 2 + 1]);
            }
        }
    }
}

// ---------------------------------------------------------------------------
// fp16 flash attention + fused LayerNorm — 64-ROW q-tiles (halves cp.async
// op count, the measured bottleneck), 512 threads, 1 CTA/SM, 4 resident
// KV chunks (R14 schedule), R12 warp geometry with rh extended to 0..3.
// smem: Q 66560 | KV 4x17408 | S/P 17408 | stats -> 156160 B.
// ---------------------------------------------------------------------------
#define SD 68        // S pitch fp32
#define PP 72        // P pitch fp16

#define OQ  0                    /* 64 x 1040B = 66560 */
#define OCB 66560                /* 4 bufs x 17408 -> 136192 */
#define OSP 136192               /* S 64x68 fp32 (17408), P overlays */
#define OPH 136192               /* fp16 64x72 = 9216 */
#define OAL 153600               /* fp32 64 */
#define OLL 153856               /* fp32 64 */
#define ORS 154112               /* fp32 64x4 = 1024 */
#define ORQ 155136               /* fp32 64x4 = 1024 */
#define ATTN_SMEM 156160

#define NEG_INF __int_as_float(0xff800000)

// Load one 64-key x 128-d fp16 chunk of K or V into buffer `buf` (0..3).
// 1024 x 16B units / 512 threads = 2 per thread.
__device__ __forceinline__ void attn_load_chunk(unsigned sb, int buf,
                                                const __half* Xf,
                                                size_t srow0, int dc, int tid)
{
#pragma unroll
    for (int i = 0; i < 2; i++) {
        int idx = tid + i * 512;          // 0..1023
        int row = idx >> 4;               // 0..63 (key)
        int c = idx & 15;                 // 16B unit within 128 d (256B)
        const __half* src = Xf + (srow0 + row) * 512 + dc * 128 + c * 8;
        unsigned dst = sb + OCB + buf * 17408 + row * 272 + c * 16;
        cpa16(dst, src);
    }
    cp_commit();
}

__global__ __launch_bounds__(512, 1)
void attn_mma(const float* __restrict__ gamma, const float* __restrict__ beta,
              float* __restrict__ out)
{
    extern __shared__ char smc[];
    unsigned sb = smem_u32(smc);
    float* S    = (float*)(smc + OSP);
    float* AL   = (float*)(smc + OAL);
    float* LL   = (float*)(smc + OLL);
    float* RS   = (float*)(smc + ORS);
    float* RQ   = (float*)(smc + ORQ);
    __half* PH  = (__half*)(smc + OPH);

    const int b   = blockIdx.y;
    const int qb  = gridDim.x - 1 - blockIdx.x;     // heavy tiles first
    const int tid = threadIdx.x;
    const int lane = tid & 31;
    const int w    = tid >> 5;      // 0..15
    const int rh   = w >> 2;        // 0..3 (16-row group)
    const int cg   = w & 3;         // S col group (16 cols)
    const int vg   = w & 3;         // PV col group (32 d-cols per 128-d chunk)
    const int ti = tid >> 4;        // 0..31 -> rows 2ti, 2ti+1
    const int tj = tid & 15;        // cols 4tj..4tj+3

    const size_t qrow0 = (size_t)b * SEQ + (size_t)qb * 64;

    // --- load Q (64 x 512 fp16): 4096 units / 512 = 8 per thread ---
#pragma unroll
    for (int i = 0; i < 8; i++) {
        int idx = tid + i * 512;          // 0..4095
        int row = idx >> 6;               // 0..63
        int c = idx & 63;
        const __half* src = g_qf + (qrow0 + row) * 512 + c * 8;
        unsigned dst = sb + OQ + row * 1040 + c * 16;
        cpa16(dst, src);
    }
    cp_commit();

    // PV accumulator: acc[dc][nt][4] — 16 rows x (dc*128 + vg*32 + nt*8) cols
    float acc[4][4][4];
#pragma unroll
    for (int d = 0; d < 4; d++)
#pragma unroll
        for (int nt = 0; nt < 4; nt++)
#pragma unroll
            for (int k = 0; k < 4; k++) acc[d][nt][k] = 0.0f;

    float m0r = NEG_INF, m1r = NEG_INF;
    float l0r = 0.0f,    l1r = 0.0f;

    const unsigned frow   = (lane & 7) + ((lane >> 3) & 1) * 8;
    const unsigned qrow_a = rh * 16 + frow;
    const unsigned kca    = ((lane >> 4) & 1) * 8;
    const unsigned krow4  = cg * 16 + ((lane >> 4) & 1) * 8 + (lane & 7);
    const unsigned kc4    = ((lane >> 3) & 1) * 8;
    const unsigned psel   = ((lane >> 4) & 1) * 8;
    const unsigned vsrow  = ((lane >> 3) & 1) * 8 + (lane & 7);
    const unsigned vdoff  = ((lane >> 4) & 1) * 8;

    const int jbmax = qb;   // 64-key tiles; diagonal = qb

    // prologue: issue all 4 K chunks of jb=0
#pragma unroll
    for (int dc = 0; dc < 4; dc++)
        attn_load_chunk(sb, dc, g_kf, (size_t)b * SEQ, dc, tid);

    for (int jb = 0; jb <= jbmax; jb++) {
        const size_t srow0 = (size_t)b * SEQ + (size_t)jb * 64;
        const bool last = (jb == jbmax);

        cp_wait<0>();
        __syncthreads();

        // ---- S phase: warp (rh, cg) = 16 rows x 16 cols, full K ----
        float s0[4] = {0, 0, 0, 0};
        float s1[4] = {0, 0, 0, 0};
#pragma unroll
        for (int dc = 0; dc < 4; dc++) {
            unsigned kb = sb + OCB + dc * 17408;
#pragma unroll
            for (int ks = 0; ks < 8; ks++) {
                unsigned qcol = (dc * 128 + ks * 16 + kca) * 2;
                unsigned Qf[4], Kf[4];
                ldsm4(Qf, sb + OQ + qrow_a * 1040 + qcol);
                unsigned kcol = (ks * 16 + kc4) * 2;
                ldsm4(Kf, kb + krow4 * 272 + kcol);
                mma_f16(s0, Qf, Kf[0], Kf[1]);
                mma_f16(s1, Qf, Kf[2], Kf[3]);
            }
        }
        // write S fragments
        {
            int r  = lane >> 2;
            int c2 = (lane & 3) * 2;
            int row0 = rh * 16 + r;
            int col0 = cg * 16 + c2;
            *(float2*)&S[row0 * SD + col0]           = make_float2(s0[0], s0[1]);
            *(float2*)&S[(row0 + 8) * SD + col0]     = make_float2(s0[2], s0[3]);
            *(float2*)&S[row0 * SD + col0 + 8]       = make_float2(s1[0], s1[1]);
            *(float2*)&S[(row0 + 8) * SD + col0 + 8] = make_float2(s1[2], s1[3]);
        }
        __syncthreads();   // S visible; K buffers free

        // issue all 4 V chunks — overlaps softmax
#pragma unroll
        for (int dc = 0; dc < 4; dc++)
            attn_load_chunk(sb, dc, g_vf, srow0, dc, tid);

        // ---- softmax (rows 2ti, 2ti+1 x cols 4tj..4tj+3; covers 64x64) ----
        {
            float4 v0 = *(float4*)&S[(2 * ti) * SD + 4 * tj];
            float4 v1 = *(float4*)&S[(2 * ti + 1) * SD + 4 * tj];
            float a0[4] = {v0.x, v0.y, v0.z, v0.w};
            float a1[4] = {v1.x, v1.y, v1.z, v1.w};

            if (jb == jbmax) {
                int qi0 = qb * 64 + 2 * ti;
                int kj  = jb * 64 + 4 * tj;
#pragma unroll
                for (int c = 0; c < 4; c++) {
                    if (kj + c > qi0)     a0[c] = NEG_INF;
                    if (kj + c > qi0 + 1) a1[c] = NEG_INF;
                }
            }

            float r0 = fmaxf(fmaxf(a0[0], a0[1]), fmaxf(a0[2], a0[3]));
            float r1 = fmaxf(fmaxf(a1[0], a1[1]), fmaxf(a1[2], a1[3]));
#pragma unroll
            for (int off = 1; off < 16; off <<= 1) {
                r0 = fmaxf(r0, __shfl_xor_sync(0xffffffffu, r0, off));
                r1 = fmaxf(r1, __shfl_xor_sync(0xffffffffu, r1, off));
            }
            float mn0 = fmaxf(m0r, r0);
            float mn1 = fmaxf(m1r, r1);
            float al0 = __expf(m0r - mn0);
            float al1 = __expf(m1r - mn1);

            float p0[4], p1[4];
#pragma unroll
            for (int c = 0; c < 4; c++) {
                p0[c] = __expf(a0[c] - mn0);
                p1[c] = __expf(a1[c] - mn1);
            }
            float rs0 = (p0[0] + p0[1]) + (p0[2] + p0[3]);
            float rs1 = (p1[0] + p1[1]) + (p1[2] + p1[3]);
#pragma unroll
            for (int off = 1; off < 16; off <<= 1) {
                rs0 += __shfl_xor_sync(0xffffffffu, rs0, off);
                rs1 += __shfl_xor_sync(0xffffffffu, rs1, off);
            }
            l0r = al0 * l0r + rs0;  m0r = mn0;
            l1r = al1 * l1r + rs1;  m1r = mn1;

            if (tj == 0) {
                AL[2 * ti]     = al0;
                AL[2 * ti + 1] = al1;
                LL[2 * ti]     = l0r;
                LL[2 * ti + 1] = l1r;
            }
            __syncthreads();   // all S reads done before P overlays S

            *(__half2*)&PH[(2 * ti) * PP + 4 * tj]         = __floats2half2_rn(p0[0], p0[1]);
            *(__half2*)&PH[(2 * ti) * PP + 4 * tj + 2]     = __floats2half2_rn(p0[2], p0[3]);
            *(__half2*)&PH[(2 * ti + 1) * PP + 4 * tj]     = __floats2half2_rn(p1[0], p1[1]);
            *(__half2*)&PH[(2 * ti + 1) * PP + 4 * tj + 2] = __floats2half2_rn(p1[2], p1[3]);
        }
        __syncthreads();   // P + AL visible

        // hoist P fragments into registers (warp rows = rh*16 block)
        unsigned Pf[4][4];
#pragma unroll
        for (int ks2 = 0; ks2 < 4; ks2++) {
            unsigned pcol = (ks2 * 16 + psel) * 2;
            ldsm4(Pf[ks2], sb + OPH + qrow_a * 144 + pcol);
        }

        // scale accumulators by alpha
        {
            float a0 = AL[rh * 16 + (lane >> 2)];
            float a1 = AL[rh * 16 + (lane >> 2) + 8];
#pragma unroll
            for (int d = 0; d < 4; d++)
#pragma unroll
                for (int nt = 0; nt < 4; nt++) {
                    acc[d][nt][0] *= a0; acc[d][nt][1] *= a0;
                    acc[d][nt][2] *= a1; acc[d][nt][3] *= a1;
                }
        }

        // ---- wait for V, one long PV burst ----
        cp_wait<0>();
        __syncthreads();
#pragma unroll
        for (int dc = 0; dc < 4; dc++) {
            unsigned vb = sb + OCB + dc * 17408;
#pragma unroll
            for (int ks2 = 0; ks2 < 4; ks2++) {
                unsigned vrow = (ks2 * 16 + vsrow) * 272;
#pragma unroll
                for (int ng2 = 0; ng2 < 2; ng2++) {
                    unsigned vcol = (vg * 32 + ng2 * 16 + vdoff) * 2;
                    unsigned Vf[4];
                    ldsm4t(Vf, vb + vrow + vcol);
                    mma_f16(acc[dc][ng2 * 2],     Pf[ks2], Vf[0], Vf[1]);
                    mma_f16(acc[dc][ng2 * 2 + 1], Pf[ks2], Vf[2], Vf[3]);
                }
            }
        }
        __syncthreads();   // V buffers free

        if (!last) {
#pragma unroll
            for (int dc = 0; dc < 4; dc++)
                attn_load_chunk(sb, dc, g_kf, srow0 + 64, dc, tid);
        }
    }

    // ---- epilogue: 1/l, LayerNorm, store ----
    {
        int r  = lane >> 2;
        int c2 = (lane & 3) * 2;
        int row0 = rh * 16 + r;
        int row1 = row0 + 8;
        float linv0 = 1.0f / LL[row0];
        float linv1 = 1.0f / LL[row1];
        float s0 = 0.f, q0 = 0.f, s1 = 0.f, q1 = 0.f;
#pragma unroll
        for (int d = 0; d < 4; d++)
#pragma unroll
            for (int nt = 0; nt < 4; nt++) {
                acc[d][nt][0] *= linv0; acc[d][nt][1] *= linv0;
                acc[d][nt][2] *= linv1; acc[d][nt][3] *= linv1;
                s0 += acc[d][nt][0] + acc[d][nt][1];
                q0 += acc[d][nt][0] * acc[d][nt][0] + acc[d][nt][1] * acc[d][nt][1];
                s1 += acc[d][nt][2] + acc[d][nt][3];
                q1 += acc[d][nt][2] * acc[d][nt][2] + acc[d][nt][3] * acc[d][nt][3];
            }
#pragma unroll
        for (int off = 1; off < 4; off <<= 1) {
            s0 += __shfl_xor_sync(0xffffffffu, s0, off);
            q0 += __shfl_xor_sync(0xffffffffu, q0, off);
            s1 += __shfl_xor_sync(0xffffffffu, s1, off);
            q1 += __shfl_xor_sync(0xffffffffu, q1, off);
        }
        if ((lane & 3) == 0) {
            RS[row0 * 4 + vg] = s0;  RQ[row0 * 4 + vg] = q0;
            RS[row1 * 4 + vg] = s1;  RQ[row1 * 4 + vg] = q1;
        }
        __syncthreads();
        float ts0 = RS[row0 * 4] + RS[row0 * 4 + 1] + RS[row0 * 4 + 2] + RS[row0 * 4 + 3];
        float tq0 = RQ[row0 * 4] + RQ[row0 * 4 + 1] + RQ[row0 * 4 + 2] + RQ[row0 * 4 + 3];
        float ts1 = RS[row1 * 4] + RS[row1 * 4 + 1] + RS[row1 * 4 + 2] + RS[row1 * 4 + 3];
        float tq1 = RQ[row1 * 4] + RQ[row1 * 4 + 1] + RQ[row1 * 4 + 2] + RQ[row1 * 4 + 3];
        const float invD = 1.0f / (float)DIM;
        float mu0 = ts0 * invD, var0 = tq0 * invD - mu0 * mu0;
        float mu1 = ts1 * invD, var1 = tq1 * invD - mu1 * mu1;
        float rstd0 = rsqrtf(var0 + 1e-5f);
        float rstd1 = rsqrtf(var1 + 1e-5f);

        size_t ob0 = (qrow0 + row0) * 512;
        size_t ob1 = (qrow0 + row1) * 512;
#pragma unroll
        for (int d = 0; d < 4; d++)
#pragma unroll
            for (int nt = 0; nt < 4; nt++) {
                int col = d * 128 + vg * 32 + nt * 8 + c2;
                float g0 = gamma[col], g1 = gamma[col + 1];
                float be0 = beta[col], be1 = beta[col + 1];
                float2 o0 = make_float2((acc[d][nt][0] - mu0) * rstd0 * g0 + be0,
                                        (acc[d][nt][1] - mu0) * rstd0 * g1 + be1);
                float2 o1 = make_float2((acc[d][nt][2] - mu1) * rstd1 * g0 + be0,
                                        (acc[d][nt][3] - mu1) * rstd1 * g1 + be1);
                *(float2*)(out + ob0 + col) = o0;
                *(float2*)(out + ob1 + col) = o1;
            }
    }
}

// ---------------------------------------------------------------------------
// Launch
// ---------------------------------------------------------------------------
extern "C" void kernel_launch(void* const* d_in, const int* in_sizes, int n_in,
                              void* d_out, int out_size)
{
    const float* x0    = (const float*)d_in[0];
    const float* x1    = (const float*)d_in[1];
    const float* Wq    = (const float*)d_in[2];
    const float* Wk    = (const float*)d_in[3];
    const float* Wv    = (const float*)d_in[4];
    const float* gamma = (const float*)d_in[5];
    const float* beta  = (const float*)d_in[6];
    float* out = (float*)d_out;

    cudaFuncSetAttribute(qkv_hmma, cudaFuncAttributeMaxDynamicSharedMemorySize, GF_SMEM);
    cudaFuncSetAttribute(attn_mma, cudaFuncAttributeMaxDynamicSharedMemorySize, ATTN_SMEM);

    conv_x<<<MTOT, 256>>>(x0, x1);
    conv_w<<<dim3(16, 32, 3), dim3(32, 8)>>>(Wq, Wk, Wv);
    qkv_hmma<<<dim3(12, 128), 256, GF_SMEM>>>();
    attn_mma<<<dim3(SEQ / 64, BATCH), 512, ATTN_SMEM>>>(gamma, beta, out);
}